// round 8
// baseline (speedup 1.0000x reference)
#include <cuda_runtime.h>
#include <cuda_fp16.h>
#include <math.h>

#define TWO_PI 6.283185307179586f

// ---- static device scratch (allocation-free) ----
// FFT intermediates (after v-axis transform), channel-last fp16: A[u][v][c]
__device__ __align__(16) __half2 g_A0[256 * 256 * 128];  // 33.5 MB each
__device__ __align__(16) __half2 g_A1[256 * 256 * 128];
__device__ __align__(16) __half2 g_A2[256 * 256 * 128];
// Sampled volumes, channel-last fp16: V[u][v][c]
__device__ __align__(16) __half2 g_Vx[256 * 256 * 128];
__device__ __align__(16) __half2 g_Vy[256 * 256 * 128];
__device__ __align__(16) __half2 g_Vz[256 * 256 * 128];

#define SH_R 273   // smem row stride (float2 units)

// ---------------------------------------------------------------------------
// complex helpers
// ---------------------------------------------------------------------------
__device__ __forceinline__ float2 cmul(float2 a, float2 b) {
    return make_float2(fmaf(a.x, b.x, -a.y * b.y), fmaf(a.x, b.y, a.y * b.x));
}
__device__ __forceinline__ float2 cmul_imm(float2 a, float c, float s) {
    return make_float2(fmaf(a.x, c, a.y * (-s)), fmaf(a.y, c, a.x * s));
}
__device__ __forceinline__ float2 cadd(float2 a, float2 b) { return make_float2(a.x + b.x, a.y + b.y); }
__device__ __forceinline__ float2 csub(float2 a, float2 b) { return make_float2(a.x - b.x, a.y - b.y); }
__device__ __forceinline__ float2 muli(float2 a) { return make_float2(-a.y, a.x); }

__device__ __forceinline__ void dft4(float2 x0, float2 x1, float2 x2, float2 x3,
                                     float2& X0, float2& X1, float2& X2, float2& X3) {
    float2 t0 = cadd(x0, x2), t1 = csub(x0, x2);
    float2 t2 = cadd(x1, x3), t3 = csub(x1, x3);
    X0 = cadd(t0, t2);
    X2 = csub(t0, t2);
    float2 it3 = muli(t3);
    X1 = cadd(t1, it3);
    X3 = csub(t1, it3);
}

// inverse 16-point DFT, radix-4x4, natural-order in/out.
__device__ __forceinline__ void ifft16(const float2 x[16], float2 X[16]) {
    const float C  = 0.70710678118654752f;
    const float c1 = 0.92387953251128676f;
    const float s1 = 0.38268343236508977f;
    float2 y[16];
#pragma unroll
    for (int k1 = 0; k1 < 4; ++k1)
        dft4(x[k1], x[k1 + 4], x[k1 + 8], x[k1 + 12],
             y[4 * k1 + 0], y[4 * k1 + 1], y[4 * k1 + 2], y[4 * k1 + 3]);
    y[4 * 1 + 1] = cmul_imm(y[4 * 1 + 1],  c1,  s1);
    y[4 * 1 + 2] = cmul_imm(y[4 * 1 + 2],   C,   C);
    y[4 * 1 + 3] = cmul_imm(y[4 * 1 + 3],  s1,  c1);
    y[4 * 2 + 1] = cmul_imm(y[4 * 2 + 1],   C,   C);
    y[4 * 2 + 2] = muli(y[4 * 2 + 2]);
    y[4 * 2 + 3] = cmul_imm(y[4 * 2 + 3],  -C,   C);
    y[4 * 3 + 1] = cmul_imm(y[4 * 3 + 1],  s1,  c1);
    y[4 * 3 + 2] = cmul_imm(y[4 * 3 + 2],  -C,   C);
    y[4 * 3 + 3] = cmul_imm(y[4 * 3 + 3], -c1, -s1);
#pragma unroll
    for (int n2 = 0; n2 < 4; ++n2) {
        float2 z0, z1, z2, z3;
        dft4(y[4 * 0 + n2], y[4 * 1 + n2], y[4 * 2 + n2], y[4 * 3 + n2], z0, z1, z2, z3);
        X[n2] = z0; X[4 + n2] = z1; X[8 + n2] = z2; X[12 + n2] = z3;
    }
}

// 256-point inverse DFT core: stage-1 input x[k1] already in registers.
// On exit sh[line][v] holds the transformed line (v = output index).
__device__ __forceinline__ void fft256_core(const float2 x[16], float2 (*sh)[SH_R],
                                            int line, int k0) {
    float2 X[16];
    ifft16(x, X);
    float sb, cb;
    __sincosf((float)k0 * (TWO_PI / 256.f), &sb, &cb);
    float2 base = make_float2(cb, sb);
    float2 tw = make_float2(1.f, 0.f);
#pragma unroll
    for (int n0 = 0; n0 < 16; ++n0) {
        sh[line][k0 * 17 + n0] = cmul(X[n0], tw);
        tw = cmul(tw, base);
    }
    __syncthreads();
    const int n0 = k0;
    float2 y[16];
#pragma unroll
    for (int kk = 0; kk < 16; ++kk) y[kk] = sh[line][kk * 17 + n0];
    __syncthreads();
    float2 Y[16];
    ifft16(y, Y);
#pragma unroll
    for (int n1 = 0; n1 < 16; ++n1) sh[line][n1 * 16 + n0] = Y[n1];
    __syncthreads();
}

// ----------------------------------------------------------------------------
// Pass 1 (all 3 volumes): inverse DFT along contiguous axis v.
// ----------------------------------------------------------------------------
__global__ __launch_bounds__(256) void k_fft_pass1_all(
        const float* __restrict__ x_re, const float* __restrict__ x_im,
        const float* __restrict__ y_re, const float* __restrict__ y_im,
        const float* __restrict__ z_re, const float* __restrict__ z_im,
        const float* __restrict__ alphap) {
    __shared__ float2 sh[16][SH_R];
    const int t = threadIdx.x;
    const int line = t >> 4, k0 = t & 15;

    const float ap = alphap[0];
    const float bxx = 10.f * ap;
    const float alpha = (bxx > 1.f) ? ap : 0.1f * log1pf(expf(fminf(bxx, 30.f)));

    const int bb = blockIdx.x;
    const int mode = bb >> 11;
    const int b = bb & 2047;
    const int u = b & 255;
    const int c0 = (b >> 8) * 16;

    float2 x[16];
    if (mode == 2) {
        const int f0 = c0 >> 3;
        const int base = f0 * 524288 + u * 2048;
#pragma unroll
        for (int j = 0; j < 16; ++j) {
            int e = t + 256 * j;                  // 0..4095
            int f_loc = e >> 11, r = e & 2047;
            int d = r & 7, v = r >> 3;
            sh[f_loc * 8 + d][v] = make_float2(z_re[base + f_loc * 524288 + r] * alpha,
                                               z_im[base + f_loc * 524288 + r] * alpha);
        }
        __syncthreads();
#pragma unroll
        for (int k1 = 0; k1 < 16; ++k1) x[k1] = sh[line][k1 * 16 + k0];
        __syncthreads();
    } else {
        const float* __restrict__ re = (mode == 0) ? x_re : y_re;
        const float* __restrict__ im = (mode == 0) ? x_im : y_im;
        int c = c0 + line;
        int base;
        if (mode == 0) base = c * 65536 + u * 256;
        else           base = (c >> 3) * 524288 + u * 2048 + (c & 7) * 256;
#pragma unroll
        for (int k1 = 0; k1 < 16; ++k1) {
            int idx = base + k1 * 16 + k0;
            x[k1] = make_float2(re[idx] * alpha, im[idx] * alpha);
        }
    }
    fft256_core(x, sh, line, k0);

    __half2* __restrict__ A = (mode == 0) ? g_A0 : (mode == 1) ? g_A1 : g_A2;
#pragma unroll
    for (int j = 0; j < 16; ++j) {
        int e = t + 256 * j;
        int cl = e & 15, v = e >> 4;
        float2 val = sh[cl][v];
        A[(u * 256 + v) * 128 + c0 + cl] = __floats2half2_rn(val.x, val.y);
    }
}

// ----------------------------------------------------------------------------
// Pass 2 (all 3 volumes): inverse DFT along u. Block = 16 channels at one v.
// ----------------------------------------------------------------------------
__global__ __launch_bounds__(256) void k_fft_pass2_all() {
    __shared__ float2 sh[16][SH_R];
    const int t = threadIdx.x;
    const int line = t >> 4, k0 = t & 15;

    const int bb = blockIdx.x;
    const int mode = bb >> 11;
    const int b = bb & 2047;
    const int v = b & 255;
    const int c0 = (b >> 8) * 16;

    const __half2* __restrict__ A = (mode == 0) ? g_A0 : (mode == 1) ? g_A1 : g_A2;
    __half2* __restrict__ V = (mode == 0) ? g_Vx : (mode == 1) ? g_Vy : g_Vz;

#pragma unroll
    for (int j = 0; j < 16; ++j) {
        int e = t + 256 * j;
        int cl = e & 15, u = e >> 4;
        sh[cl][u] = __half22float2(A[(u * 256 + v) * 128 + c0 + cl]);
    }
    __syncthreads();
    float2 x[16];
#pragma unroll
    for (int k1 = 0; k1 < 16; ++k1) x[k1] = sh[line][k1 * 16 + k0];
    __syncthreads();
    fft256_core(x, sh, line, k0);

#pragma unroll
    for (int j = 0; j < 16; ++j) {
        int e = t + 256 * j;
        int cl = e & 15, u = e >> 4;
        float2 val = sh[cl][u];
        V[(u * 256 + v) * 128 + c0 + cl] = __floats2half2_rn(val.x, val.y);
    }
}

// ----------------------------------------------------------------------------
// Sampling, plane-partitioned: blocks [0,16384) -> plane X, [16384,32768) ->
// plane Y, [32768,49152) -> plane Z. Block-index order keeps the resident
// wave inside ONE 100MB volume -> it L2-caches instead of thrashing.
// Each warp computes one plane's contribution for one point; RED.F32 adds.
// ----------------------------------------------------------------------------
__device__ __forceinline__ int corner_base(float gu, float gv, int& u1d, int& v1d,
                                           float& wu, float& wv) {
    float iu = (gu + 1.f) * 127.5f;
    float iv = (gv + 1.f) * 127.5f;
    float u0f = floorf(iu), v0f = floorf(iv);
    wu = iu - u0f; wv = iv - v0f;
    int u0 = (int)u0f; u0 = max(0, min(u0, 255)); int u1 = min(u0 + 1, 255);
    int v0 = (int)v0f; v0 = max(0, min(v0, 255)); int v1 = min(v0 + 1, 255);
    u1d = (u1 - u0) * 256 * 128;
    v1d = (v1 - v0) * 128;
    return (u0 * 256 + v0) * 128;
}

__global__ __launch_bounds__(256) void k_sample_planes(const float* __restrict__ pts,
                                                       float* __restrict__ out) {
    const int bb = blockIdx.x;
    const int plane = bb >> 14;              // 16384 blocks per plane
    const int pb = bb & 16383;
    const int gw = pb * 8 + ((threadIdx.x) >> 5);   // point index
    const int lane = threadIdx.x & 31;

    float xs = pts[gw * 3 + 0];
    float ys = pts[gw * 3 + 1];
    float zs = pts[gw * 3 + 2];

    float gu, gv, tx;
    const __half2* __restrict__ V;
    if (plane == 0)      { V = g_Vx; gu = ys; gv = zs; tx = xs; }
    else if (plane == 1) { V = g_Vy; gu = xs; gv = zs; tx = ys; }
    else                 { V = g_Vz; gu = xs; gv = ys; tx = zs; }

    int cbase = lane * 4;
    int d0 = cbase & 7;

    float wu, wv;
    int u1d, v1d;
    int base = corner_base(gu, gv, u1d, v1d, wu, wv) + cbase;

    uint4 q00 = *(const uint4*)(V + base);
    uint4 q01 = *(const uint4*)(V + base + v1d);
    uint4 q10 = *(const uint4*)(V + base + u1d);
    uint4 q11 = *(const uint4*)(V + base + u1d + v1d);

    float w00 = (1.f - wu) * (1.f - wv), w01 = (1.f - wu) * wv;
    float w10 = wu * (1.f - wv),         w11 = wu * wv;

    const float K = TWO_PI * 0.5f * (255.f / 256.f);
    float bang = (tx + 1.f) * K;
    float sn1, cn1;
    __sincosf(bang, &sn1, &cn1);
    float2 w1 = make_float2(cn1, sn1);
    float2 w2 = cmul(w1, w1);
    float2 w4 = cmul(w2, w2);
    float2 cur = (d0 == 0) ? make_float2(1.f, 0.f) : w4;

    const unsigned* a00 = (const unsigned*)&q00;
    const unsigned* a01 = (const unsigned*)&q01;
    const unsigned* a10 = (const unsigned*)&q10;
    const unsigned* a11 = (const unsigned*)&q11;

    float acc = 0.f;
#pragma unroll
    for (int j = 0; j < 4; ++j) {
        float2 a = __half22float2(*(const __half2*)&a00[j]);
        float2 b = __half22float2(*(const __half2*)&a01[j]);
        float2 c = __half22float2(*(const __half2*)&a10[j]);
        float2 d = __half22float2(*(const __half2*)&a11[j]);
        float sr = w00 * a.x + w01 * b.x + w10 * c.x + w11 * d.x;
        float si = w00 * a.y + w01 * b.y + w10 * c.y + w11 * d.y;
        float sc = (d0 + j > 0) ? 2.f : 1.f;
        acc += sc * (sr * cur.x - si * cur.y);
        cur = cmul(cur, w1);
    }

    // pair (2f, 2f+1) -> feature f
    acc += __shfl_xor_sync(0xffffffffu, acc, 1);
    float vv = __shfl_sync(0xffffffffu, acc, (lane & 15) * 2);
    if (lane < 16) atomicAdd(&out[gw * 16 + lane], vv);
}

extern "C" void kernel_launch(void* const* d_in, const int* in_sizes, int n_in,
                              void* d_out, int out_size) {
    const float* pts    = (const float*)d_in[0];
    const float* Fx_re  = (const float*)d_in[1];
    const float* Fx_im  = (const float*)d_in[2];
    const float* Fy_re  = (const float*)d_in[3];
    const float* Fy_im  = (const float*)d_in[4];
    const float* Fz_re  = (const float*)d_in[5];
    const float* Fz_im  = (const float*)d_in[6];
    const float* alphap = (const float*)d_in[7];
    float* out = (float*)d_out;

    cudaMemsetAsync(out, 0, (size_t)out_size * sizeof(float), 0);
    k_fft_pass1_all<<<6144, 256>>>(Fx_re, Fx_im, Fy_re, Fy_im, Fz_re, Fz_im, alphap);
    k_fft_pass2_all<<<6144, 256>>>();
    k_sample_planes<<<3 * 16384, 256>>>(pts, out);
}